// round 9
// baseline (speedup 1.0000x reference)
#include <cuda_runtime.h>
#include <math.h>

// DTW loss, LEN=2048, squared-difference cost, out = sqrt(DTW[N-1][N-1]).
//
// Bidirectional decomposition (exact): any monotone path crosses row
// 1023 -> 1024 exactly once, so
//   DTW^2 = min_j ( F[1023][j] + min(B[1024][j], B[1024][j+1]) )
// F = forward DP rows 0..1023; B = backward DP rows 1024..2047 = forward DP
// on (reverse(x), reverse(y)):  B[1024][j] = G[1023][2047-j].
//
// One kernel, grid=2 (CTA0 = F, CTA1 = G). Systolic column DP: NT=128
// threads, 16 cols/thread, 4 rows/step, 383 steps. FULLY UNIFORM control
// flow: the block index is clamped and all threads compute every step —
// out-of-range blocks run on all-INF state, which is exactly the virtual
// border (fma(d,d,INF)=INF, fmin(INF,INF)=INF, d finite => no NaN).
// Each thread publishes its final row at the unique step b==NBLK-1
// (predicated stores), after which its registers may be freely corrupted.
// Boundary handoff: parity double-buffered float4 smem with a guard slot
// (slot 0 = INF) so thread 0 needs no special case. One barrier per step.
// Last CTA to finish fuses the min-plus combine.
//
// Per-cell (4 instr, fma/alu pipes balanced):
//   d = xi + (-y_j); m = fmin(up, dg); mm = fmin(m, left); v = fma(d,d,mm)

#define LEN   2048
#define HALF  1024
#define NT    128
#define CPT   16                   // columns per thread
#define RPS   4                    // rows per step
#define NBLK  (HALF / RPS)         // 256
#define STEPS (NBLK + NT - 1)      // 383

__device__ float g_rows[2][LEN];   // [0]=F row 1023, [1]=G row 1023 (reversed idx)
__device__ int   g_ctr = 0;        // completion counter (reset each launch)

__global__ __launch_bounds__(NT, 1)
void dtw_fused_kernel(const float* __restrict__ x,
                      const float* __restrict__ y,
                      float* __restrict__ out)
{
    __shared__ float4 xs4[HALF / 4];      // this half's x rows (4 KB)
    __shared__ float4 buf[2][NT + 1];     // parity handoff + guard slot 0
    __shared__ float  red[NT / 32];
    __shared__ int    amLast;

    const int tid = threadIdx.x;
    const int dir = blockIdx.x;           // 0 = forward half, 1 = reversed half
    const float INF = __int_as_float(0x7f800000);

    // Preload x rows for this half (forward: x[0..1023]; reversed: x[2047..1024]).
    {
        float* xs = reinterpret_cast<float*>(xs4);
        if (dir == 0) {
            for (int i = tid; i < HALF; i += NT) xs[i] = x[i];
        } else {
            for (int i = tid; i < HALF; i += NT) xs[i] = x[LEN - 1 - i];
        }
    }
    // Init handoff buffers (both parities, all slots incl. guard) to INF.
    {
        float4 inf4 = make_float4(INF, INF, INF, INF);
        for (int i = tid; i < 2 * (NT + 1); i += NT)
            (&buf[0][0])[i] = inf4;
    }

    // Column-strip state in registers (reversed y for the backward half).
    float negY[CPT], up[CPT];
#pragma unroll
    for (int j = 0; j < CPT; ++j) {
        const int col = tid * CPT + j;
        negY[j] = -((dir == 0) ? y[col] : y[LEN - 1 - col]);
        up[j]   = INF;                   // virtual row -1
    }

    // diag entering first row of the next block: v[4b-1][16t-1].
    // Thread 0, block 0: corner (-1,-1) = 0. Otherwise +inf.
    float diag = (tid == 0) ? 0.0f : INF;

    float* gout = &g_rows[dir][tid * CPT];

    __syncthreads();

    for (int s = 0; s < STEPS; ++s) {
        const int b   = s - tid;
        const int bc  = min(max(b, 0), NBLK - 1);   // clamped: uniform flow
        const int par = s & 1;

        // Neighbor's last-column values for my 4 rows (written step s-1).
        // Slot tid; guard slot 0 stays INF (virtual column for thread 0).
        const float4 L  = buf[par ^ 1][tid];
        const float4 xv = xs4[bc];
        const float lx[4] = {L.x, L.y, L.z, L.w};
        const float xr[4] = {xv.x, xv.y, xv.z, xv.w};
        float pb[4];

        float dgen = diag;               // diag entering first row of block
#pragma unroll
        for (int k = 0; k < RPS; ++k) {
            float left = lx[k];
            float dg   = dgen;
            const float xi = xr[k];
#pragma unroll
            for (int j = 0; j < CPT; ++j) {
                const float d  = xi + negY[j];     // FADD
                const float m  = fminf(up[j], dg); // off-chain FMNMX
                const float mm = fminf(m, left);   // chain FMNMX
                const float v  = fmaf(d, d, mm);   // chain FFMA
                dg    = up[j];                     // reg rename (free)
                up[j] = v;
                left  = v;
            }
            pb[k] = left;                // my last-column value, row 4bc+k
            dgen  = lx[k];               // neighbor row k -> diag for row k+1
        }
        diag = lx[3];                    // diag entering next block's first row

        buf[par][tid + 1] = make_float4(pb[0], pb[1], pb[2], pb[3]);

        // Publish final row exactly once, before later garbage corrupts up[].
        if (b == NBLK - 1) {
#pragma unroll
            for (int j = 0; j < CPT; ++j) gout[j] = up[j];
        }
        __syncthreads();
    }

    // ── fused combine: last CTA to finish does the min-plus join ──
    __threadfence();                     // release g_rows writes
    if (tid == 0) {
        int old = atomicAdd(&g_ctr, 1);
        amLast = (old == 1);
    }
    __syncthreads();
    if (!amLast) return;
    __threadfence();                     // acquire: order reads after atomic

    // term_j = F[1023][j] + min(B[1024][j], B[1024][j+1]),
    // B[1024][j] = g_rows[1][LEN-1-j], B[1024][LEN] = +inf.
    float m = INF;
#pragma unroll
    for (int k = 0; k < LEN / NT; ++k) {
        const int j = tid + k * NT;
        const float F  = g_rows[0][j];
        const float B0 = g_rows[1][LEN - 1 - j];
        const float B1 = (j + 1 < LEN) ? g_rows[1][LEN - 2 - j] : INF;
        m = fminf(m, F + fminf(B0, B1));
    }
#pragma unroll
    for (int o = 16; o; o >>= 1)
        m = fminf(m, __shfl_xor_sync(0xFFFFFFFFu, m, o));
    if ((tid & 31) == 0) red[tid >> 5] = m;
    __syncthreads();
    if (tid == 0) {
        float v = fminf(fminf(red[0], red[1]), fminf(red[2], red[3]));
        out[0] = sqrtf(v);
        g_ctr  = 0;                      // reset for next graph replay
    }
}

extern "C" void kernel_launch(void* const* d_in, const int* in_sizes, int n_in,
                              void* d_out, int out_size)
{
    (void)in_sizes; (void)n_in; (void)out_size;
    const float* x = (const float*)d_in[0];
    const float* y = (const float*)d_in[1];
    float* out = (float*)d_out;
    dtw_fused_kernel<<<2, NT>>>(x, y, out);
}

// round 10
// speedup vs baseline: 1.0757x; 1.0757x over previous
#include <cuda_runtime.h>
#include <math.h>

// DTW loss, LEN=2048, squared-difference cost, out = sqrt(DTW[N-1][N-1]).
//
// Bidirectional decomposition (exact): any monotone path crosses row
// 1023 -> 1024 exactly once, so
//   DTW^2 = min_j ( F[1023][j] + min(B[1024][j], B[1024][j+1]) )
// F = forward DP rows 0..1023; B = backward DP on (reverse(x), reverse(y)):
// B[1024][j] = G[1023][2047-j].  One kernel, grid=2 (CTA0=F, CTA1=G).
//
// Systolic column DP per CTA: NT=128 threads, 16 cols/thread, 4 rows/step,
// 383 steps. Uniform control flow: block index clamped; out-of-range blocks
// run on all-INF state == virtual border (fma(d,d,INF)=INF, d finite).
// Step loop split in two phases:
//   A: s in [0,256)   — no thread is past its last block: publish-free body.
//   B: s in [256,383) — exactly one thread publishes per step (guarded).
// Unrolled by 2 so the parity double-buffer addresses are loop-invariant;
// next step's x row is prefetched into registers before the barrier.
//
// Per-cell (4 instr, fma/alu balanced):
//   d = xi + (-y_j); m = fmin(up, dg); mm = fmin(m, left); v = fma(d,d,mm)

#define LEN   2048
#define HALF  1024
#define NT    128
#define CPT   16                   // columns per thread
#define RPS   4                    // rows per step
#define NBLK  (HALF / RPS)         // 256
#define STEPS (NBLK + NT - 1)      // 383

__device__ float g_rows[2][LEN];   // [0]=F row 1023, [1]=G row 1023 (reversed idx)
__device__ int   g_ctr = 0;        // completion counter (reset each launch)

__global__ __launch_bounds__(NT, 1)
void dtw_fused_kernel(const float* __restrict__ x,
                      const float* __restrict__ y,
                      float* __restrict__ out)
{
    __shared__ float4 xs4[HALF / 4];      // this half's x rows (4 KB)
    __shared__ float4 buf[2][NT + 1];     // parity handoff + guard slot 0
    __shared__ float  red[NT / 32];
    __shared__ int    amLast;

    const int tid = threadIdx.x;
    const int dir = blockIdx.x;           // 0 = forward half, 1 = reversed half
    const float INF = __int_as_float(0x7f800000);

    // Preload x rows for this half (forward: x[0..1023]; reversed: x[2047..1024]).
    {
        float* xs = reinterpret_cast<float*>(xs4);
        if (dir == 0) {
            for (int i = tid; i < HALF; i += NT) xs[i] = x[i];
        } else {
            for (int i = tid; i < HALF; i += NT) xs[i] = x[LEN - 1 - i];
        }
    }
    // Init handoff buffers (both parities, all slots incl. guard) to INF.
    {
        float4 inf4 = make_float4(INF, INF, INF, INF);
        for (int i = tid; i < 2 * (NT + 1); i += NT)
            (&buf[0][0])[i] = inf4;
    }

    // Column-strip state in registers (reversed y for the backward half).
    float negY[CPT], up[CPT];
#pragma unroll
    for (int j = 0; j < CPT; ++j) {
        const int col = tid * CPT + j;
        negY[j] = -((dir == 0) ? y[col] : y[LEN - 1 - col]);
        up[j]   = INF;                   // virtual row -1
    }

    // diag entering first row of the next block: v[4b-1][16t-1].
    // Thread 0, block 0: corner (-1,-1) = 0. Otherwise +inf.
    float diag = (tid == 0) ? 0.0f : INF;

    float* gout = &g_rows[dir][tid * CPT];
    float4* const b0 = &buf[0][0];
    float4* const b1 = &buf[1][0];

    __syncthreads();

    // Prefetched x rows for the current step (bc(s=0) = max(-tid,0) = 0).
    float4 xv = xs4[0];

    // One systolic step. rb/wb are the parity read/write buffers (compile-time
    // constant per call site); pub enables the final-row publish (phase B).
    auto step_body = [&](int s, const float4* rb, float4* wb, bool pub) {
        const int b = s - tid;
        const float4 L = rb[tid];        // neighbor's last-col values (guard=INF)
        const float lx[4] = {L.x, L.y, L.z, L.w};
        const float xr[4] = {xv.x, xv.y, xv.z, xv.w};
        float pb[4];

        float dgen = diag;               // diag entering first row of block
#pragma unroll
        for (int k = 0; k < RPS; ++k) {
            float left = lx[k];
            float dg   = dgen;
            const float xi = xr[k];
#pragma unroll
            for (int j = 0; j < CPT; ++j) {
                const float d  = xi + negY[j];     // FADD
                const float m  = fminf(up[j], dg); // off-chain FMNMX
                const float mm = fminf(m, left);   // chain FMNMX
                const float v  = fmaf(d, d, mm);   // chain FFMA
                dg    = up[j];                     // reg rename (free)
                up[j] = v;
                left  = v;
            }
            pb[k] = left;
            dgen  = lx[k];
        }
        diag = lx[3];

        wb[tid + 1] = make_float4(pb[0], pb[1], pb[2], pb[3]);

        // Prefetch next step's x rows (independent of the barrier).
        const int bn = min(max(s + 1 - tid, 0), NBLK - 1);
        xv = xs4[bn];

        if (pub) {
            // Unique publishing thread this step: t = s - (NBLK-1).
            if (b == NBLK - 1) {
#pragma unroll
                for (int j = 0; j < CPT; ++j) gout[j] = up[j];
            }
        }
        __syncthreads();
    };

    // Phase A: s in [0, NBLK) — publish-free, unrolled by 2 (static parity:
    // even s writes buf[0]/reads buf[1]; odd s the reverse).
    for (int s = 0; s < NBLK; s += 2) {
        step_body(s,     b1, b0, false);
        step_body(s + 1, b0, b1, false);
    }
    // Thread 0 finished block NBLK-1 at s = NBLK-1.
    if (tid == 0) {
#pragma unroll
        for (int j = 0; j < CPT; ++j) gout[j] = up[j];
    }
    // Phase B: s in [NBLK, STEPS) — 127 steps, guarded publish; 63 pairs + peel.
    for (int s = NBLK; s < STEPS - 1; s += 2) {
        step_body(s,     b1, b0, true);
        step_body(s + 1, b0, b1, true);
    }
    step_body(STEPS - 1, b1, b0, true);   // s=382 (even parity)

    // ── fused combine: last CTA to finish does the min-plus join ──
    __threadfence();                     // release g_rows writes
    if (tid == 0) {
        int old = atomicAdd(&g_ctr, 1);
        amLast = (old == 1);
    }
    __syncthreads();
    if (!amLast) return;
    __threadfence();                     // acquire: order reads after atomic

    // term_j = F[1023][j] + min(B[1024][j], B[1024][j+1]),
    // B[1024][j] = g_rows[1][LEN-1-j], B[1024][LEN] = +inf.
    float m = INF;
#pragma unroll
    for (int k = 0; k < LEN / NT; ++k) {
        const int j = tid + k * NT;
        const float F  = g_rows[0][j];
        const float B0 = g_rows[1][LEN - 1 - j];
        const float B1 = (j + 1 < LEN) ? g_rows[1][LEN - 2 - j] : INF;
        m = fminf(m, F + fminf(B0, B1));
    }
#pragma unroll
    for (int o = 16; o; o >>= 1)
        m = fminf(m, __shfl_xor_sync(0xFFFFFFFFu, m, o));
    if ((tid & 31) == 0) red[tid >> 5] = m;
    __syncthreads();
    if (tid == 0) {
        float v = fminf(fminf(red[0], red[1]), fminf(red[2], red[3]));
        out[0] = sqrtf(v);
        g_ctr  = 0;                      // reset for next graph replay
    }
}

extern "C" void kernel_launch(void* const* d_in, const int* in_sizes, int n_in,
                              void* d_out, int out_size)
{
    (void)in_sizes; (void)n_in; (void)out_size;
    const float* x = (const float*)d_in[0];
    const float* y = (const float*)d_in[1];
    float* out = (float*)d_out;
    dtw_fused_kernel<<<2, NT>>>(x, y, out);
}